// round 4
// baseline (speedup 1.0000x reference)
#include <cuda_runtime.h>
#include <cstdint>

// Problem constants (fixed by reference)
#define NN    16384   // n_nodes
#define D_IN  128
#define D_H   64
#define BB    4096    // minibatch

// Device scratch (no allocations allowed)
__device__ float g_enc[NN * D_H];      // 4 MiB: encoder output
__device__ float g_rowout[NN * D_H];   // 4 MiB: per-unique-row results
__device__ int   g_idx[BB];
__device__ int   g_rows[BB];           // unique row worklist
__device__ int   g_flag[NN];
__device__ int   g_nuniq;
__device__ int   g_work;

// ---------------------------------------------------------------------------
// K1 prep: zero flags/counters + decode idx (int64 vs int32).
// Detection window is IDENTICAL and IN-BOUNDS for every decode block: odd
// int32 words of entries 0..255 (word idx 1..511 — safe whether the buffer
// is 4096 int32 words or 8192). int64 with values <16384 => all zero;
// P(false positive | int32) = (1/16384)^256 ~ 0. All blocks reach the same
// verdict deterministically, then decode their own 256-entry slice.
// ---------------------------------------------------------------------------
__global__ void __launch_bounds__(256) prep_kernel(const int* __restrict__ idx32) {
    const int b = blockIdx.x, tid = threadIdx.x;
    if (b < 16) {
        // zero flags: 16384 / 16 blocks = 1024 per block
#pragma unroll
        for (int u = 0; u < 4; u++) g_flag[b * 1024 + u * 256 + tid] = 0;
        if (b == 0 && tid == 0) { g_nuniq = 0; g_work = 0; }
    } else {
        __shared__ int s_is64;
        if (tid == 0) s_is64 = 1;
        __syncthreads();
        if (idx32[2 * tid + 1] != 0) s_is64 = 0;   // safe window; benign race
        __syncthreads();
        const int i = (b - 16) * 256 + tid;
        g_idx[i] = s_is64 ? idx32[2 * i] : idx32[i];
    }
}

// ---------------------------------------------------------------------------
// K2: enc = X @ W + b -> g_enc [NN,64]; 4 extra blocks build the unique-row
// worklist from g_idx (stream-ordered after K1).
// ---------------------------------------------------------------------------
__global__ void __launch_bounds__(256) enc_kernel(const float* __restrict__ X,
                                                  const float* __restrict__ W,
                                                  const float* __restrict__ b) {
    if (blockIdx.x >= NN / 32) {
        // ---- unique-row build: 4 blocks x 256 threads x 4 entries ----
        const int base = (blockIdx.x - NN / 32) * 1024 + threadIdx.x;
#pragma unroll
        for (int u = 0; u < 4; u++) {
            const int row = g_idx[base + u * 256];
            if (atomicExch(&g_flag[row], 1) == 0) {
                const int p = atomicAdd(&g_nuniq, 1);
                g_rows[p] = row;
            }
        }
        return;
    }

    __shared__ float sW[D_IN * D_H];   // 32 KiB
    __shared__ float sX[32 * D_IN];    // 16 KiB
    const int tid = threadIdx.x;

    for (int i = tid; i < D_IN * D_H; i += 256) sW[i] = W[i];
    const int row0 = blockIdx.x * 32;
    for (int i = tid; i < 32 * D_IN; i += 256) sX[i] = X[(size_t)row0 * D_IN + i];
    __syncthreads();

    const int c  = tid & 63;
    const int r0 = tid >> 6;           // 0..3
    const float bc = b[c];
    float acc[8];
#pragma unroll
    for (int a = 0; a < 8; a++) acc[a] = bc;

#pragma unroll 4
    for (int k = 0; k < D_IN; k++) {
        const float w = sW[k * D_H + c];
#pragma unroll
        for (int a = 0; a < 8; a++)
            acc[a] += sX[(r0 + 4 * a) * D_IN + k] * w;
    }
#pragma unroll
    for (int a = 0; a < 8; a++)
        g_enc[(size_t)(row0 + r0 + 4 * a) * D_H + c] = acc[a];
}

// ---------------------------------------------------------------------------
// K3: persistent gather. Blocks pop unique rows off g_work; per row, 4 warps
// stream 1/4 of the 64KB ppr row (8 uint4 in flight/lane, streaming loads,
// integer-OR zero test), append nonzeros to per-warp smem lists, replay lists
// against L2-resident g_enc, reduce, write g_rowout[row].
// ---------------------------------------------------------------------------
__global__ void __launch_bounds__(128) gather_kernel(const float* __restrict__ ppr) {
    __shared__ float vbuf[4][192];
    __shared__ int   jbuf[4][192];
    __shared__ int   cnt[4];
    __shared__ float red[4][D_H];
    __shared__ int   s_widx;

    const int lane = threadIdx.x & 31;
    const int warp = threadIdx.x >> 5;
    const int nuniq = g_nuniq;

    for (;;) {
        if (threadIdx.x == 0) s_widx = atomicAdd(&g_work, 1);
        __syncthreads();
        const int widx = s_widx;
        if (widx >= nuniq) break;
        const int row = g_rows[widx];

        if (lane == 0) cnt[warp] = 0;
        __syncwarp();

        const uint4* rowp = reinterpret_cast<const uint4*>(ppr) + (size_t)row * (NN / 4);
        const int base = warp * (NN / 16);   // 1024 float4 per warp

        // ---- Phase 1: stream + extract nonzeros ----
        for (int it = 0; it < 32; it += 8) {
            uint4 buf[8];
#pragma unroll
            for (int u = 0; u < 8; u++)
                buf[u] = __ldcs(rowp + base + (it + u) * 32 + lane);

#pragma unroll
            for (int u = 0; u < 8; u++) {
                const uint4 q = buf[u];
                if (q.x | q.y | q.z | q.w) {
                    const int j0 = (base + (it + u) * 32 + lane) * 4;
                    if (q.x) { int p = atomicAdd(&cnt[warp], 1); if (p < 192) { jbuf[warp][p] = j0;     vbuf[warp][p] = __uint_as_float(q.x); } }
                    if (q.y) { int p = atomicAdd(&cnt[warp], 1); if (p < 192) { jbuf[warp][p] = j0 + 1; vbuf[warp][p] = __uint_as_float(q.y); } }
                    if (q.z) { int p = atomicAdd(&cnt[warp], 1); if (p < 192) { jbuf[warp][p] = j0 + 2; vbuf[warp][p] = __uint_as_float(q.z); } }
                    if (q.w) { int p = atomicAdd(&cnt[warp], 1); if (p < 192) { jbuf[warp][p] = j0 + 3; vbuf[warp][p] = __uint_as_float(q.w); } }
                }
            }
        }
        __syncwarp();

        // ---- Phase 2: replay nonzero list ----
        float acc0 = 0.0f, acc1 = 0.0f;
        const int n = min(cnt[warp], 192);
        for (int k = 0; k < n; k++) {
            const float v = vbuf[warp][k];
            const float* er = g_enc + (size_t)jbuf[warp][k] * D_H;
            acc0 += v * __ldg(er + lane);
            acc1 += v * __ldg(er + lane + 32);
        }

        red[warp][lane]      = acc0;
        red[warp][lane + 32] = acc1;
        __syncthreads();
        if (threadIdx.x < D_H) {
            const int c = threadIdx.x;
            g_rowout[(size_t)row * D_H + c] = red[0][c] + red[1][c] + red[2][c] + red[3][c];
        }
        __syncthreads();   // protect smem reuse on next iteration
    }
}

// ---------------------------------------------------------------------------
// K4 scatter: out[i,:] = g_rowout[idx[i],:]  (1 MiB, L2-resident)
// ---------------------------------------------------------------------------
__global__ void __launch_bounds__(256) scatter_kernel(float* __restrict__ out) {
    const int e = blockIdx.x * 256 + threadIdx.x;   // element in [0, BB*D_H)
    const int i = e >> 6;
    const int c = e & 63;
    out[e] = g_rowout[(size_t)g_idx[i] * D_H + c];
}

// ---------------------------------------------------------------------------
extern "C" void kernel_launch(void* const* d_in, const int* in_sizes, int n_in,
                              void* d_out, int out_size) {
    const float* X   = (const float*)d_in[0];
    const float* ppr = (const float*)d_in[1];
    const float* W   = (const float*)d_in[2];
    const float* b   = (const float*)d_in[3];
    const int*   idx = (const int*)d_in[4];   // decoded in-kernel (int32 or int64)
    float* out = (float*)d_out;

    prep_kernel<<<32, 256>>>(idx);
    enc_kernel<<<NN / 32 + 4, 256>>>(X, W, b);
    gather_kernel<<<148 * 12, 128>>>(ppr);
    scatter_kernel<<<BB * D_H / 256, 256>>>(out);
}